// round 3
// baseline (speedup 1.0000x reference)
#include <cuda_runtime.h>

// Problem constants
#define N_IMG 256   // B*T = 32*8
#define C_IN  128
#define K_OUT 128
#define HH    32
#define WW    32

// Conv tiling
#define KTILE  32   // output channels per block
#define RTILE  8    // output rows per block
#define CCHUNK 16   // input channels per smem stage

// Conv intermediate: y[n][k][h][w], n = b*8 + t  (128 MiB scratch, __device__ global)
__device__ float g_y[(size_t)N_IMG * K_OUT * HH * WW];

// ---------------------------------------------------------------------------
// Kernel 1: 3x3 SAME conv, fp32 direct, smem-tiled.
// Block = 256 threads = 8 k-groups x 32 columns.
// Each thread: 4 output channels x 8 rows (one column) = 32 master accs
// + 32 chunk-partial accs (hierarchical accumulation: chain length 144 at
// small magnitude instead of 1152 at full magnitude -> ~5x smaller rounding
// error, which controls spike-flip count in the downstream discretizer).
// ---------------------------------------------------------------------------
__global__ __launch_bounds__(256, 2)
void conv3x3_kernel(const float* __restrict__ x,
                    const float* __restrict__ W,
                    const float* __restrict__ bias)
{
    __shared__ float xs[CCHUNK][RTILE + 2][WW + 2];     // 21.25 KiB
    __shared__ float ws[KTILE * CCHUNK * 9];            // 18    KiB

    const int n     = blockIdx.x;
    const int kbase = blockIdx.y * KTILE;
    const int hbase = blockIdx.z * RTILE;
    const int tid   = threadIdx.x;
    const int col   = tid & 31;    // output column (0..31)
    const int kg    = tid >> 5;    // k-group (0..7), uniform within a warp

    float acc[4][8];               // master accumulators
#pragma unroll
    for (int i = 0; i < 4; i++)
#pragma unroll
        for (int r = 0; r < 8; r++) acc[i][r] = 0.f;

    for (int cb = 0; cb < C_IN; cb += CCHUNK) {
        __syncthreads();  // previous chunk's compute done before overwrite

        // Stage x chunk with halo (zero-pad SAME borders)
        for (int idx = tid; idx < CCHUNK * (RTILE + 2) * (WW + 2); idx += 256) {
            int c   = idx / ((RTILE + 2) * (WW + 2));
            int rem = idx % ((RTILE + 2) * (WW + 2));
            int rr  = rem / (WW + 2);
            int cc  = rem % (WW + 2);
            int gh  = hbase + rr - 1;
            int gw  = cc - 1;
            float v = 0.f;
            if (gh >= 0 && gh < HH && gw >= 0 && gw < WW)
                v = x[(((size_t)n * C_IN + cb + c) * HH + gh) * WW + gw];
            xs[c][rr][cc] = v;
        }
        // Stage weight chunk: W is [K][C][3][3]
        for (int idx = tid; idx < KTILE * CCHUNK * 9; idx += 256) {
            int k   = idx / (CCHUNK * 9);
            int rem = idx % (CCHUNK * 9);
            int c   = rem / 9;
            int rs  = rem % 9;
            ws[(k * CCHUNK + c) * 9 + rs] =
                W[((size_t)(kbase + k) * C_IN + cb + c) * 9 + rs];
        }
        __syncthreads();

        // Chunk-partial accumulators (hierarchical summation)
        float pacc[4][8];
#pragma unroll
        for (int i = 0; i < 4; i++)
#pragma unroll
            for (int r = 0; r < 8; r++) pacc[i][r] = 0.f;

#pragma unroll 1
        for (int c = 0; c < CCHUNK; c++) {
#pragma unroll
            for (int s = 0; s < 3; s++) {
                float xr[10];
#pragma unroll
                for (int rr = 0; rr < 10; rr++) xr[rr] = xs[c][rr][col + s];
#pragma unroll
                for (int r = 0; r < 3; r++) {
                    const int wb = c * 9 + r * 3 + s;
                    float w0 = ws[((kg * 4 + 0) * CCHUNK) * 9 + wb];
                    float w1 = ws[((kg * 4 + 1) * CCHUNK) * 9 + wb];
                    float w2 = ws[((kg * 4 + 2) * CCHUNK) * 9 + wb];
                    float w3 = ws[((kg * 4 + 3) * CCHUNK) * 9 + wb];
#pragma unroll
                    for (int row = 0; row < 8; row++) {
                        float xv = xr[row + r];
                        pacc[0][row] += w0 * xv;
                        pacc[1][row] += w1 * xv;
                        pacc[2][row] += w2 * xv;
                        pacc[3][row] += w3 * xv;
                    }
                }
            }
        }

        // Fold chunk partial into master (one rounding per chunk)
#pragma unroll
        for (int i = 0; i < 4; i++)
#pragma unroll
            for (int r = 0; r < 8; r++) acc[i][r] += pacc[i][r];
    }

    // Epilogue: bias + store to scratch (coalesced over col)
#pragma unroll
    for (int i = 0; i < 4; i++) {
        int k  = kbase + kg * 4 + i;
        float bv = bias[k];
#pragma unroll
        for (int row = 0; row < 8; row++) {
            g_y[(((size_t)n * K_OUT + k) * HH + hbase + row) * WW + col] =
                acc[i][row] + bv;
        }
    }
}

// ---------------------------------------------------------------------------
// Kernel 2: spiking scan over T=8. One thread handles 4 consecutive (c,h,w)
// elements of one batch b via float4 (memory-bound; fully coalesced).
// Fire, soft reset, then inhibition (negative spike) — matches reference.
// ---------------------------------------------------------------------------
__global__ void spike_scan_kernel(const float* __restrict__ thr_p,
                                  float* __restrict__ out)
{
    const int PER_B4 = (C_IN * HH * WW) / 4;   // 32768 float4 groups per batch
    int idx = blockIdx.x * blockDim.x + threadIdx.x;
    if (idx >= 32 * PER_B4) return;

    const float thr = thr_p[0];
    int b = idx >> 15;            // idx / 32768
    int g = idx & 32767;          // idx % 32768

    const float4* y4 = (const float4*)g_y;
    float4*       o4 = (float4*)out;
    size_t base = (size_t)(b * 8) * PER_B4 + g;

    float mem[4], sum[4];
#pragma unroll
    for (int j = 0; j < 4; j++) { mem[j] = 0.5f * thr; sum[j] = 0.f; }

#pragma unroll
    for (int t = 0; t < 8; t++) {
        float4 v = y4[base + (size_t)t * PER_B4];
        float xin[4] = {v.x, v.y, v.z, v.w};
        float o[4];
#pragma unroll
        for (int j = 0; j < 4; j++) {
            mem[j] += xin[j];
            float sp = (mem[j] >= thr) ? 1.f : 0.f;
            mem[j] -= thr * sp;
            sum[j] += sp;
            float inh = ((mem[j] <= -0.001f) && (sum[j] > 0.f)) ? 1.f : 0.f;
            mem[j] += thr * inh;
            sum[j] -= inh;
            o[j] = (sp - inh) * thr;
        }
        float4 ov = make_float4(o[0], o[1], o[2], o[3]);
        o4[base + (size_t)t * PER_B4] = ov;
    }
}

// ---------------------------------------------------------------------------
// Launch: inputs are x, W, b, threshold (metadata order). Output float32
// [B, T, C, H, W] = 33554432 elements, same linear layout as g_y.
// ---------------------------------------------------------------------------
extern "C" void kernel_launch(void* const* d_in, const int* in_sizes, int n_in,
                              void* d_out, int out_size)
{
    const float* x    = (const float*)d_in[0];
    const float* W    = (const float*)d_in[1];
    const float* bias = (const float*)d_in[2];
    const float* thr  = (const float*)d_in[3];
    float* out        = (float*)d_out;

    dim3 grid(N_IMG, K_OUT / KTILE, HH / RTILE);   // 256 x 4 x 4 = 4096 blocks
    conv3x3_kernel<<<grid, 256>>>(x, W, bias);

    int groups = 32 * (C_IN * HH * WW) / 4;        // 1,048,576 threads
    spike_scan_kernel<<<groups / 256, 256>>>(thr, out);
}

// round 4
// speedup vs baseline: 1.0153x; 1.0153x over previous
#include <cuda_runtime.h>
#include <cstdint>

// Problem constants
#define N_IMG 256   // B*T = 32*8
#define C_IN  128
#define K_OUT 128
#define HH    32
#define WW    32

// Conv tiling
#define KTILE  32   // output channels per block
#define RTILE  8    // output rows per block
#define CCHUNK 16   // input channels per smem stage

// Conv intermediate: y[n][k][h][w], n = b*8 + t  (128 MiB scratch, __device__ global)
__device__ float g_y[(size_t)N_IMG * K_OUT * HH * WW];

// ---- packed f32x2 helpers (Blackwell sm_103a; ptxas never emits these from C++) ----
__device__ __forceinline__ void fma2(unsigned long long& acc,
                                     unsigned long long a,
                                     unsigned long long b) {
    asm("fma.rn.f32x2 %0, %1, %2, %0;" : "+l"(acc) : "l"(a), "l"(b));
}
__device__ __forceinline__ void add2(unsigned long long& acc,
                                     unsigned long long a) {
    asm("add.rn.f32x2 %0, %1, %0;" : "+l"(acc) : "l"(a));
}
__device__ __forceinline__ unsigned long long splat2(float v) {
    unsigned long long r;
    asm("mov.b64 %0, {%1, %1};" : "=l"(r) : "r"(__float_as_uint(v)));
    return r;
}
__device__ __forceinline__ void unpack2(float& lo, float& hi, unsigned long long v) {
    unsigned int a, b;
    asm("mov.b64 {%0, %1}, %2;" : "=r"(a), "=r"(b) : "l"(v));
    lo = __uint_as_float(a);
    hi = __uint_as_float(b);
}

// ---------------------------------------------------------------------------
// Kernel 1: 3x3 SAME conv, fp32 direct, smem-tiled, packed-FFMA2 inner loop.
// Block = 256 threads = 8 k-groups x 32 columns.
// Each thread: 4 output channels (as 2 packed k-pairs) x 8 rows.
// Weights staged in shared with k innermost so a k-pair is one LDS.64
// (warp-uniform address -> broadcast). x values splatted {v,v} once per
// column-register and reused over 3 vertical taps and both k-pairs.
// Hierarchical accumulation preserved (chunk partials) -> same rounding as R3.
// ---------------------------------------------------------------------------
__global__ __launch_bounds__(256, 2)
void conv3x3_kernel(const float* __restrict__ x,
                    const float* __restrict__ W,
                    const float* __restrict__ bias)
{
    __shared__ float xs[CCHUNK][RTILE + 2][WW + 2];          // 21.25 KiB
    __shared__ __align__(8) float ws_raw[CCHUNK * 9 * KTILE]; // 18 KiB, [c][tap][k]

    const int n     = blockIdx.x;
    const int kbase = blockIdx.y * KTILE;
    const int hbase = blockIdx.z * RTILE;
    const int tid   = threadIdx.x;
    const int col   = tid & 31;    // output column (0..31)
    const int kg    = tid >> 5;    // k-group (0..7), uniform within a warp

    // acc2[p][row] = packed {k = kg*4+2p, k+1} master accumulators
    unsigned long long acc2[2][8];
#pragma unroll
    for (int p = 0; p < 2; p++)
#pragma unroll
        for (int r = 0; r < 8; r++) acc2[p][r] = 0ull;

    for (int cb = 0; cb < C_IN; cb += CCHUNK) {
        __syncthreads();  // previous chunk's compute done before overwrite

        // Stage x chunk with halo (zero-pad SAME borders)
        for (int idx = tid; idx < CCHUNK * (RTILE + 2) * (WW + 2); idx += 256) {
            int c   = idx / ((RTILE + 2) * (WW + 2));
            int rem = idx % ((RTILE + 2) * (WW + 2));
            int rr  = rem / (WW + 2);
            int cc  = rem % (WW + 2);
            int gh  = hbase + rr - 1;
            int gw  = cc - 1;
            float v = 0.f;
            if (gh >= 0 && gh < HH && gw >= 0 && gw < WW)
                v = x[(((size_t)n * C_IN + cb + c) * HH + gh) * WW + gw];
            xs[c][rr][cc] = v;
        }
        // Stage weight chunk: W is [K][C][3][3]; shared layout [c][tap][k]
        // so consecutive k are adjacent (LDS.64 loads a k-pair).
        for (int idx = tid; idx < CCHUNK * 9 * KTILE; idx += 256) {
            int c   = idx / (9 * KTILE);
            int rem = idx % (9 * KTILE);
            int tap = rem / KTILE;
            int k   = rem % KTILE;
            ws_raw[idx] = W[((size_t)(kbase + k) * C_IN + cb + c) * 9 + tap];
        }
        __syncthreads();

        const unsigned long long* ws2 = (const unsigned long long*)ws_raw;

        // Chunk-partial accumulators (hierarchical summation)
        unsigned long long pacc2[2][8];
#pragma unroll
        for (int p = 0; p < 2; p++)
#pragma unroll
            for (int r = 0; r < 8; r++) pacc2[p][r] = 0ull;

#pragma unroll 1
        for (int c = 0; c < CCHUNK; c++) {
#pragma unroll
            for (int s = 0; s < 3; s++) {
                // Column of x at horizontal tap s, splatted for packed FMA
                unsigned long long x2[10];
#pragma unroll
                for (int rr = 0; rr < 10; rr++)
                    x2[rr] = splat2(xs[c][rr][col + s]);
#pragma unroll
                for (int r = 0; r < 3; r++) {
                    const int tap = r * 3 + s;
                    // k-pairs for this thread's 4 output channels
                    unsigned long long wA = ws2[(c * 9 + tap) * (KTILE / 2) + kg * 2 + 0];
                    unsigned long long wB = ws2[(c * 9 + tap) * (KTILE / 2) + kg * 2 + 1];
#pragma unroll
                    for (int row = 0; row < 8; row++) {
                        fma2(pacc2[0][row], wA, x2[row + r]);
                        fma2(pacc2[1][row], wB, x2[row + r]);
                    }
                }
            }
        }

        // Fold chunk partial into master (one rounding per chunk)
#pragma unroll
        for (int p = 0; p < 2; p++)
#pragma unroll
            for (int r = 0; r < 8; r++) add2(acc2[p][r], pacc2[p][r]);
    }

    // Epilogue: bias + store to scratch (coalesced over col)
#pragma unroll
    for (int p = 0; p < 2; p++) {
        int k0 = kbase + kg * 4 + 2 * p;
        float b0 = bias[k0];
        float b1 = bias[k0 + 1];
#pragma unroll
        for (int row = 0; row < 8; row++) {
            float lo, hi;
            unpack2(lo, hi, acc2[p][row]);
            g_y[(((size_t)n * K_OUT + k0)     * HH + hbase + row) * WW + col] = lo + b0;
            g_y[(((size_t)n * K_OUT + k0 + 1) * HH + hbase + row) * WW + col] = hi + b1;
        }
    }
}

// ---------------------------------------------------------------------------
// Kernel 2: spiking scan over T=8. One thread handles 4 consecutive (c,h,w)
// elements of one batch b via float4 (memory-bound; 74% DRAM — near roofline).
// Fire, soft reset, then inhibition (negative spike) — matches reference.
// ---------------------------------------------------------------------------
__global__ void spike_scan_kernel(const float* __restrict__ thr_p,
                                  float* __restrict__ out)
{
    const int PER_B4 = (C_IN * HH * WW) / 4;   // 32768 float4 groups per batch
    int idx = blockIdx.x * blockDim.x + threadIdx.x;
    if (idx >= 32 * PER_B4) return;

    const float thr = thr_p[0];
    int b = idx >> 15;            // idx / 32768
    int g = idx & 32767;          // idx % 32768

    const float4* y4 = (const float4*)g_y;
    float4*       o4 = (float4*)out;
    size_t base = (size_t)(b * 8) * PER_B4 + g;

    float mem[4], sum[4];
#pragma unroll
    for (int j = 0; j < 4; j++) { mem[j] = 0.5f * thr; sum[j] = 0.f; }

#pragma unroll
    for (int t = 0; t < 8; t++) {
        float4 v = y4[base + (size_t)t * PER_B4];
        float xin[4] = {v.x, v.y, v.z, v.w};
        float o[4];
#pragma unroll
        for (int j = 0; j < 4; j++) {
            mem[j] += xin[j];
            float sp = (mem[j] >= thr) ? 1.f : 0.f;
            mem[j] -= thr * sp;
            sum[j] += sp;
            float inh = ((mem[j] <= -0.001f) && (sum[j] > 0.f)) ? 1.f : 0.f;
            mem[j] += thr * inh;
            sum[j] -= inh;
            o[j] = (sp - inh) * thr;
        }
        float4 ov = make_float4(o[0], o[1], o[2], o[3]);
        o4[base + (size_t)t * PER_B4] = ov;
    }
}

// ---------------------------------------------------------------------------
// Launch: inputs are x, W, b, threshold (metadata order). Output float32
// [B, T, C, H, W] = 33554432 elements, same linear layout as g_y.
// ---------------------------------------------------------------------------
extern "C" void kernel_launch(void* const* d_in, const int* in_sizes, int n_in,
                              void* d_out, int out_size)
{
    const float* x    = (const float*)d_in[0];
    const float* W    = (const float*)d_in[1];
    const float* bias = (const float*)d_in[2];
    const float* thr  = (const float*)d_in[3];
    float* out        = (float*)d_out;

    dim3 grid(N_IMG, K_OUT / KTILE, HH / RTILE);   // 256 x 4 x 4 = 4096 blocks
    conv3x3_kernel<<<grid, 256>>>(x, W, bias);

    int groups = 32 * (C_IN * HH * WW) / 4;        // 1,048,576 threads
    spike_scan_kernel<<<groups / 256, 256>>>(thr, out);
}

// round 5
// speedup vs baseline: 1.0161x; 1.0008x over previous
#include <cuda_runtime.h>
#include <cstdint>

// Problem constants
#define N_IMG 256   // B*T = 32*8
#define C_IN  128
#define K_OUT 128
#define HH    32
#define WW    32

// Conv tiling
#define KTILE  32   // output channels per block
#define RTILE  8    // output rows per block
#define CCHUNK 16   // input channels per smem stage

// Conv intermediate: y[n][k][h][w], n = b*8 + t  (128 MiB scratch, __device__ global)
__device__ float g_y[(size_t)N_IMG * K_OUT * HH * WW];

// ---- packed f32x2 helpers (Blackwell sm_103a; ptxas never emits these from C++) ----
__device__ __forceinline__ void fma2(unsigned long long& acc,
                                     unsigned long long a,
                                     unsigned long long b) {
    asm("fma.rn.f32x2 %0, %1, %2, %0;" : "+l"(acc) : "l"(a), "l"(b));
}
__device__ __forceinline__ void add2(unsigned long long& acc,
                                     unsigned long long a) {
    asm("add.rn.f32x2 %0, %1, %0;" : "+l"(acc) : "l"(a));
}
__device__ __forceinline__ unsigned long long splat2(float v) {
    unsigned long long r;
    asm("mov.b64 %0, {%1, %1};" : "=l"(r) : "r"(__float_as_uint(v)));
    return r;
}
__device__ __forceinline__ void unpack2(float& lo, float& hi, unsigned long long v) {
    unsigned int a, b;
    asm("mov.b64 {%0, %1}, %2;" : "=r"(a), "=r"(b) : "l"(v));
    lo = __uint_as_float(a);
    hi = __uint_as_float(b);
}

// ---------------------------------------------------------------------------
// Kernel 1: 3x3 SAME conv, fp32 direct, smem-tiled, packed-FFMA2 inner loop.
// Block = 256 threads = 8 k-groups x 32 columns.
// Each thread: 4 output channels (as 2 packed k-pairs) x 8 rows.
// Weights staged in shared with k innermost so a k-pair is one LDS.64
// (warp-uniform address -> broadcast). x values splatted {v,v} once per
// column-register and reused over 3 vertical taps and both k-pairs.
// Hierarchical accumulation preserved (chunk partials) -> same rounding as R3.
// ---------------------------------------------------------------------------
__global__ __launch_bounds__(256, 2)
void conv3x3_kernel(const float* __restrict__ x,
                    const float* __restrict__ W,
                    const float* __restrict__ bias)
{
    __shared__ float xs[CCHUNK][RTILE + 2][WW + 2];          // 21.25 KiB
    __shared__ __align__(8) float ws_raw[CCHUNK * 9 * KTILE]; // 18 KiB, [c][tap][k]

    const int n     = blockIdx.x;
    const int kbase = blockIdx.y * KTILE;
    const int hbase = blockIdx.z * RTILE;
    const int tid   = threadIdx.x;
    const int col   = tid & 31;    // output column (0..31)
    const int kg    = tid >> 5;    // k-group (0..7), uniform within a warp

    // acc2[p][row] = packed {k = kg*4+2p, k+1} master accumulators
    unsigned long long acc2[2][8];
#pragma unroll
    for (int p = 0; p < 2; p++)
#pragma unroll
        for (int r = 0; r < 8; r++) acc2[p][r] = 0ull;

    for (int cb = 0; cb < C_IN; cb += CCHUNK) {
        __syncthreads();  // previous chunk's compute done before overwrite

        // Stage x chunk with halo (zero-pad SAME borders)
        for (int idx = tid; idx < CCHUNK * (RTILE + 2) * (WW + 2); idx += 256) {
            int c   = idx / ((RTILE + 2) * (WW + 2));
            int rem = idx % ((RTILE + 2) * (WW + 2));
            int rr  = rem / (WW + 2);
            int cc  = rem % (WW + 2);
            int gh  = hbase + rr - 1;
            int gw  = cc - 1;
            float v = 0.f;
            if (gh >= 0 && gh < HH && gw >= 0 && gw < WW)
                v = x[(((size_t)n * C_IN + cb + c) * HH + gh) * WW + gw];
            xs[c][rr][cc] = v;
        }
        // Stage weight chunk: W is [K][C][3][3]; shared layout [c][tap][k]
        // so consecutive k are adjacent (LDS.64 loads a k-pair).
        for (int idx = tid; idx < CCHUNK * 9 * KTILE; idx += 256) {
            int c   = idx / (9 * KTILE);
            int rem = idx % (9 * KTILE);
            int tap = rem / KTILE;
            int k   = rem % KTILE;
            ws_raw[idx] = W[((size_t)(kbase + k) * C_IN + cb + c) * 9 + tap];
        }
        __syncthreads();

        const unsigned long long* ws2 = (const unsigned long long*)ws_raw;

        // Chunk-partial accumulators (hierarchical summation)
        unsigned long long pacc2[2][8];
#pragma unroll
        for (int p = 0; p < 2; p++)
#pragma unroll
            for (int r = 0; r < 8; r++) pacc2[p][r] = 0ull;

#pragma unroll 1
        for (int c = 0; c < CCHUNK; c++) {
#pragma unroll
            for (int s = 0; s < 3; s++) {
                // Column of x at horizontal tap s, splatted for packed FMA
                unsigned long long x2[10];
#pragma unroll
                for (int rr = 0; rr < 10; rr++)
                    x2[rr] = splat2(xs[c][rr][col + s]);
#pragma unroll
                for (int r = 0; r < 3; r++) {
                    const int tap = r * 3 + s;
                    // k-pairs for this thread's 4 output channels
                    unsigned long long wA = ws2[(c * 9 + tap) * (KTILE / 2) + kg * 2 + 0];
                    unsigned long long wB = ws2[(c * 9 + tap) * (KTILE / 2) + kg * 2 + 1];
#pragma unroll
                    for (int row = 0; row < 8; row++) {
                        fma2(pacc2[0][row], wA, x2[row + r]);
                        fma2(pacc2[1][row], wB, x2[row + r]);
                    }
                }
            }
        }

        // Fold chunk partial into master (one rounding per chunk)
#pragma unroll
        for (int p = 0; p < 2; p++)
#pragma unroll
            for (int r = 0; r < 8; r++) add2(acc2[p][r], pacc2[p][r]);
    }

    // Epilogue: bias + store to scratch (coalesced over col)
#pragma unroll
    for (int p = 0; p < 2; p++) {
        int k0 = kbase + kg * 4 + 2 * p;
        float b0 = bias[k0];
        float b1 = bias[k0 + 1];
#pragma unroll
        for (int row = 0; row < 8; row++) {
            float lo, hi;
            unpack2(lo, hi, acc2[p][row]);
            g_y[(((size_t)n * K_OUT + k0)     * HH + hbase + row) * WW + col] = lo + b0;
            g_y[(((size_t)n * K_OUT + k0 + 1) * HH + hbase + row) * WW + col] = hi + b1;
        }
    }
}

// ---------------------------------------------------------------------------
// Kernel 2: spiking scan over T=8. One thread handles 4 consecutive (c,h,w)
// elements of one batch b via float4 (memory-bound; 74% DRAM — near roofline).
// Fire, soft reset, then inhibition (negative spike) — matches reference.
// ---------------------------------------------------------------------------
__global__ void spike_scan_kernel(const float* __restrict__ thr_p,
                                  float* __restrict__ out)
{
    const int PER_B4 = (C_IN * HH * WW) / 4;   // 32768 float4 groups per batch
    int idx = blockIdx.x * blockDim.x + threadIdx.x;
    if (idx >= 32 * PER_B4) return;

    const float thr = thr_p[0];
    int b = idx >> 15;            // idx / 32768
    int g = idx & 32767;          // idx % 32768

    const float4* y4 = (const float4*)g_y;
    float4*       o4 = (float4*)out;
    size_t base = (size_t)(b * 8) * PER_B4 + g;

    float mem[4], sum[4];
#pragma unroll
    for (int j = 0; j < 4; j++) { mem[j] = 0.5f * thr; sum[j] = 0.f; }

#pragma unroll
    for (int t = 0; t < 8; t++) {
        float4 v = y4[base + (size_t)t * PER_B4];
        float xin[4] = {v.x, v.y, v.z, v.w};
        float o[4];
#pragma unroll
        for (int j = 0; j < 4; j++) {
            mem[j] += xin[j];
            float sp = (mem[j] >= thr) ? 1.f : 0.f;
            mem[j] -= thr * sp;
            sum[j] += sp;
            float inh = ((mem[j] <= -0.001f) && (sum[j] > 0.f)) ? 1.f : 0.f;
            mem[j] += thr * inh;
            sum[j] -= inh;
            o[j] = (sp - inh) * thr;
        }
        float4 ov = make_float4(o[0], o[1], o[2], o[3]);
        o4[base + (size_t)t * PER_B4] = ov;
    }
}

// ---------------------------------------------------------------------------
// Launch: inputs are x, W, b, threshold (metadata order). Output float32
// [B, T, C, H, W] = 33554432 elements, same linear layout as g_y.
// ---------------------------------------------------------------------------
extern "C" void kernel_launch(void* const* d_in, const int* in_sizes, int n_in,
                              void* d_out, int out_size)
{
    const float* x    = (const float*)d_in[0];
    const float* W    = (const float*)d_in[1];
    const float* bias = (const float*)d_in[2];
    const float* thr  = (const float*)d_in[3];
    float* out        = (float*)d_out;

    dim3 grid(N_IMG, K_OUT / KTILE, HH / RTILE);   // 256 x 4 x 4 = 4096 blocks
    conv3x3_kernel<<<grid, 256>>>(x, W, bias);

    int groups = 32 * (C_IN * HH * WW) / 4;        // 1,048,576 threads
    spike_scan_kernel<<<groups / 256, 256>>>(thr, out);
}

// round 8
// speedup vs baseline: 1.6286x; 1.6027x over previous
#include <cuda_runtime.h>
#include <cuda_bf16.h>
#include <cstdint>

// Problem constants
#define N_IMG 256   // B*T = 32*8
#define C_IN  128
#define K_OUT 128
#define HH    32
#define WW    32
#define NP    34    // padded H/W

// GEMM staging
#define STAGES  18                  // 9 taps x 2 c-halves (64 c each)
#define TILE_B  16384               // one 128x64 bf16 tile (128 rows x 128B)
#define BUF_B   (6 * TILE_B)        // 3 W limbs + 3 x limbs = 96 KiB
#define SM_BUF0 1024                // bias in [0,512)
#define SM_TOTAL (SM_BUF0 + 2 * BUF_B)   // 197,632 B

// ---------------- device scratch (static allocation, allowed) ----------------
#define LSTR ((size_t)N_IMG * NP * NP * C_IN)
__device__ __align__(256) __nv_bfloat16 g_x0[LSTR];
__device__ __align__(256) __nv_bfloat16 g_x1[LSTR];
__device__ __align__(256) __nv_bfloat16 g_x2[LSTR];
#define WSTR (9 * 128 * 128)
__device__ __align__(256) __nv_bfloat16 g_w0[WSTR];
__device__ __align__(256) __nv_bfloat16 g_w1[WSTR];
__device__ __align__(256) __nv_bfloat16 g_w2[WSTR];
__device__ float g_y[(size_t)N_IMG * K_OUT * HH * WW];   // conv output, 128 MiB

// ---------------- PTX helpers ----------------
__device__ __forceinline__ uint32_t smem_u32(const void* p) {
    uint32_t a;
    asm("{ .reg .u64 t; cvta.to.shared.u64 t, %1; cvt.u32.u64 %0, t; }"
        : "=r"(a) : "l"(p));
    return a;
}
__device__ __forceinline__ void cp16(uint32_t dst, const void* src) {
    asm volatile("cp.async.cg.shared.global [%0], [%1], 16;"
                 :: "r"(dst), "l"(src) : "memory");
}
#define CP_COMMIT() asm volatile("cp.async.commit_group;" ::: "memory")
#define CP_WAIT0()  asm volatile("cp.async.wait_group 0;" ::: "memory")

__device__ __forceinline__ uint32_t swz(uint32_t off) {   // SW128 swizzle
    return off ^ ((off >> 3) & 0x70);
}

#define LDSM4(R, addr) \
    asm volatile("ldmatrix.sync.aligned.m8n8.x4.shared.b16 {%0,%1,%2,%3}, [%4];" \
        : "=r"((R)[0]), "=r"((R)[1]), "=r"((R)[2]), "=r"((R)[3]) : "r"(addr))

__device__ __forceinline__ void mma_bf16(float* d, const uint32_t* a,
                                         const uint32_t* b) {
    asm volatile(
        "mma.sync.aligned.m16n8k16.row.col.f32.bf16.bf16.f32 "
        "{%0,%1,%2,%3}, {%4,%5,%6,%7}, {%8,%9}, {%0,%1,%2,%3};"
        : "+f"(d[0]), "+f"(d[1]), "+f"(d[2]), "+f"(d[3])
        : "r"(a[0]), "r"(a[1]), "r"(a[2]), "r"(a[3]), "r"(b[0]), "r"(b[1]));
}

// ---------------------------------------------------------------------------
// Kernel A: zero-pad + transpose + bf16 3-limb split of x.
// x[n][c][h][w] fp32  ->  g_x{0,1,2}[n][hp][wp][c] bf16, hp/wp in [0,34).
// ---------------------------------------------------------------------------
__global__ void pad_split_kernel(const float* __restrict__ x)
{
    __shared__ float ts[C_IN][WW + 1];
    const int n  = blockIdx.x;
    const int hp = blockIdx.y;
    const int tid = threadIdx.x;
    const size_t obase = ((size_t)(n * NP + hp)) * NP * C_IN;

    if (hp == 0 || hp == NP - 1) {
        for (int i = tid; i < NP * C_IN; i += 256) {
            g_x0[obase + i] = __float2bfloat16(0.f);
            g_x1[obase + i] = __float2bfloat16(0.f);
            g_x2[obase + i] = __float2bfloat16(0.f);
        }
        return;
    }
    const int h = hp - 1;
    for (int i = tid; i < C_IN * WW; i += 256) {
        int c = i >> 5, w = i & 31;
        ts[c][w] = x[((size_t)(n * C_IN + c) * HH + h) * WW + w];
    }
    __syncthreads();
    for (int i = tid; i < NP * C_IN; i += 256) {
        int wp = i >> 7, c = i & 127;
        float v = (wp == 0 || wp == NP - 1) ? 0.f : ts[c][wp - 1];
        __nv_bfloat16 b0 = __float2bfloat16(v);
        float r1 = v - __bfloat162float(b0);
        __nv_bfloat16 b1 = __float2bfloat16(r1);
        float r2 = r1 - __bfloat162float(b1);
        g_x0[obase + i] = b0;
        g_x1[obase + i] = b1;
        g_x2[obase + i] = __float2bfloat16(r2);
    }
}

// ---------------------------------------------------------------------------
// Kernel B: weight limb split + relayout. W[k][c][3][3] fp32 ->
// g_w{0,1,2}[tap][k][c] bf16 (tap = r*3+s).
// ---------------------------------------------------------------------------
__global__ void wsplit_kernel(const float* __restrict__ W)
{
    int idx = blockIdx.x * blockDim.x + threadIdx.x;
    if (idx >= WSTR) return;
    int tap = idx / (128 * 128);
    int k   = (idx / 128) % 128;
    int c   = idx % 128;
    float v = W[((size_t)(k * 128 + c)) * 9 + tap];
    __nv_bfloat16 b0 = __float2bfloat16(v);
    float r1 = v - __bfloat162float(b0);
    __nv_bfloat16 b1 = __float2bfloat16(r1);
    float r2 = r1 - __bfloat162float(b1);
    g_w0[idx] = b0;
    g_w1[idx] = b1;
    g_w2[idx] = __float2bfloat16(r2);
}

// ---------------------------------------------------------------------------
// Kernel C: implicit-GEMM conv via warp-level bf16 mma.sync, 3-limb fp32
// emulation. CTA = 256 thr = 8 warps (2 M x 4 N); CTA tile M=128 k, N=128 px.
// Numerics: tensor-core fp32 accumulate is truncating, so (a) the working
// accumulator is folded into the RN master EVERY stage, and (b) within a
// stage the 5 small correction limb-products are accumulated FIRST (running
// sum ~2^-9 of total -> negligible RZ error) and the full-magnitude a0*b0
// term LAST (only 4 HW adds at full magnitude per stage, starting near 0).
// ---------------------------------------------------------------------------
__device__ __forceinline__ void stage_load(uint32_t smb, int buf, int s,
                                           int n, int hb)
{
    const int tap = s >> 1, ch = s & 1;
    const int r = tap / 3, sc = tap % 3, c0 = ch * 64;
    const uint32_t base = smb + SM_BUF0 + buf * BUF_B;
    const int tid = threadIdx.x;
    const __nv_bfloat16* wl[3] = { g_w0, g_w1, g_w2 };
    const __nv_bfloat16* xl[3] = { g_x0, g_x1, g_x2 };

    // W tiles (operand A): 128 k-rows x 64 c (128B rows), 3 limbs
    for (int q = tid; q < 3072; q += 256) {
        int l = q >> 10, rem = q & 1023, k = rem >> 3, seg = rem & 7;
        const void* src = wl[l] + (size_t)(tap * 128 + k) * 128 + c0 + seg * 8;
        cp16(base + l * TILE_B + swz(k * 128 + seg * 16), src);
    }
    // x tiles (operand B): 128 px-rows x 64 c, 3 limbs
    for (int q = tid; q < 3072; q += 256) {
        int l = q >> 10, rem = q & 1023, p = rem >> 3, seg = rem & 7;
        int hrow = hb * 4 + (p >> 5) + r;
        int wcol = (p & 31) + sc;
        const void* src = xl[l] +
            ((size_t)(n * NP + hrow) * NP + wcol) * C_IN + c0 + seg * 8;
        cp16(base + (3 + l) * TILE_B + swz(p * 128 + seg * 16), src);
    }
}

__global__ __launch_bounds__(256, 1)
void conv_mma_kernel(const float* __restrict__ bias)
{
    extern __shared__ char sm[];
    const uint32_t smb = smem_u32(sm);
    const int tid = threadIdx.x, wid = tid >> 5, lane = tid & 31;
    const int n = blockIdx.x, hb = blockIdx.y;

    if (tid < 128) ((float*)sm)[tid] = bias[tid];

    const int wm = (wid >> 2) * 64;   // k offset of warp tile
    const int wn = (wid & 3) * 32;    // px offset of warp tile

    float mast[4][4][4], work[4][4][4];
#pragma unroll
    for (int mt = 0; mt < 4; mt++)
#pragma unroll
        for (int nt = 0; nt < 4; nt++)
#pragma unroll
            for (int j = 0; j < 4; j++) { mast[mt][nt][j] = 0.f; work[mt][nt][j] = 0.f; }

    stage_load(smb, 0, 0, n, hb);
    CP_COMMIT();

    // Lane-constant address components
    const uint32_t arow = (lane & 15);
    const uint32_t acol = (lane >> 4) * 16;
    const uint32_t brow = (lane & 7) + (lane >> 4) * 8;
    const uint32_t bcol = ((lane >> 3) & 1) * 16;

#pragma unroll 1
    for (int s = 0; s < STAGES; s++) {
        CP_WAIT0();
        __syncthreads();                 // stage s staged; stage s-1 compute done
        if (s + 1 < STAGES) {
            stage_load(smb, (s + 1) & 1, s + 1, n, hb);
            CP_COMMIT();
        }

        const uint32_t abase = smb + SM_BUF0 + (s & 1) * BUF_B;
        const uint32_t bbase = abase + 3 * TILE_B;

        // ---- Phase 1: correction limb-products (small magnitude first) ----
#pragma unroll
        for (int ks = 0; ks < 4; ks++) {
            uint32_t a0[4][4], a1[4][4], a2[4][4];
#pragma unroll
            for (int mt = 0; mt < 4; mt++) {
                uint32_t ra = swz((wm + mt * 16 + arow) * 128 + ks * 32 + acol);
                LDSM4(a0[mt], abase + 0 * TILE_B + ra);
                LDSM4(a1[mt], abase + 1 * TILE_B + ra);
                LDSM4(a2[mt], abase + 2 * TILE_B + ra);
            }
            uint32_t b0[2][4], b1[2][4], b2[2][4];
#pragma unroll
            for (int ntp = 0; ntp < 2; ntp++) {
                uint32_t rb = swz((wn + ntp * 16 + brow) * 128 + ks * 32 + bcol);
                LDSM4(b0[ntp], bbase + 0 * TILE_B + rb);
                LDSM4(b1[ntp], bbase + 1 * TILE_B + rb);
                LDSM4(b2[ntp], bbase + 2 * TILE_B + rb);
            }
#pragma unroll
            for (int mt = 0; mt < 4; mt++)
#pragma unroll
                for (int nt = 0; nt < 4; nt++) {
                    const int hi = nt >> 1, off = (nt & 1) * 2;
                    mma_bf16(work[mt][nt], a0[mt], &b1[hi][off]);  // 0*1
                    mma_bf16(work[mt][nt], a1[mt], &b0[hi][off]);  // 1*0
                    mma_bf16(work[mt][nt], a1[mt], &b1[hi][off]);  // 1*1
                    mma_bf16(work[mt][nt], a0[mt], &b2[hi][off]);  // 0*2
                    mma_bf16(work[mt][nt], a2[mt], &b0[hi][off]);  // 2*0
                }
        }

        // ---- Phase 2: main term a0*b0 last (4 HW adds at full magnitude) ----
#pragma unroll
        for (int ks = 0; ks < 4; ks++) {
            uint32_t a0[4][4];
#pragma unroll
            for (int mt = 0; mt < 4; mt++) {
                uint32_t ra = swz((wm + mt * 16 + arow) * 128 + ks * 32 + acol);
                LDSM4(a0[mt], abase + 0 * TILE_B + ra);
            }
            uint32_t b0[2][4];
#pragma unroll
            for (int ntp = 0; ntp < 2; ntp++) {
                uint32_t rb = swz((wn + ntp * 16 + brow) * 128 + ks * 32 + bcol);
                LDSM4(b0[ntp], bbase + 0 * TILE_B + rb);
            }
#pragma unroll
            for (int mt = 0; mt < 4; mt++)
#pragma unroll
                for (int nt = 0; nt < 4; nt++)
                    mma_bf16(work[mt][nt], a0[mt], &b0[nt >> 1][(nt & 1) * 2]);
        }

        // ---- Fold working -> master in RN every stage ----
#pragma unroll
        for (int mt = 0; mt < 4; mt++)
#pragma unroll
            for (int nt = 0; nt < 4; nt++)
#pragma unroll
                for (int j = 0; j < 4; j++) {
                    mast[mt][nt][j] += work[mt][nt][j];
                    work[mt][nt][j] = 0.f;
                }
    }

    // Epilogue: acc(k, px) + bias[k] -> g_y[n][k][hb*128 + px], float2 stores
#pragma unroll
    for (int mt = 0; mt < 4; mt++) {
        const int k0 = wm + mt * 16 + (lane >> 2);
        const float bv0 = ((const float*)sm)[k0];
        const float bv1 = ((const float*)sm)[k0 + 8];
#pragma unroll
        for (int nt = 0; nt < 4; nt++) {
            const int px = wn + nt * 8 + (lane & 3) * 2;
            size_t g0 = ((size_t)(n * K_OUT + k0)) * (HH * WW) + hb * 128 + px;
            float2 v0 = make_float2(mast[mt][nt][0] + bv0, mast[mt][nt][1] + bv0);
            float2 v1 = make_float2(mast[mt][nt][2] + bv1, mast[mt][nt][3] + bv1);
            *(float2*)(g_y + g0) = v0;
            *(float2*)(g_y + g0 + 8 * (size_t)(HH * WW)) = v1;
        }
    }
}

// ---------------------------------------------------------------------------
// Kernel D: spiking scan over T=8 (unchanged; near HBM roofline).
// ---------------------------------------------------------------------------
__global__ void spike_scan_kernel(const float* __restrict__ thr_p,
                                  float* __restrict__ out)
{
    const int PER_B4 = (C_IN * HH * WW) / 4;   // 32768 float4 groups per batch
    int idx = blockIdx.x * blockDim.x + threadIdx.x;
    if (idx >= 32 * PER_B4) return;

    const float thr = thr_p[0];
    int b = idx >> 15;
    int g = idx & 32767;

    const float4* y4 = (const float4*)g_y;
    float4*       o4 = (float4*)out;
    size_t base = (size_t)(b * 8) * PER_B4 + g;

    float mem[4], sum[4];
#pragma unroll
    for (int j = 0; j < 4; j++) { mem[j] = 0.5f * thr; sum[j] = 0.f; }

#pragma unroll
    for (int t = 0; t < 8; t++) {
        float4 v = y4[base + (size_t)t * PER_B4];
        float xin[4] = {v.x, v.y, v.z, v.w};
        float o[4];
#pragma unroll
        for (int j = 0; j < 4; j++) {
            mem[j] += xin[j];
            float sp = (mem[j] >= thr) ? 1.f : 0.f;
            mem[j] -= thr * sp;
            sum[j] += sp;
            float inh = ((mem[j] <= -0.001f) && (sum[j] > 0.f)) ? 1.f : 0.f;
            mem[j] += thr * inh;
            sum[j] -= inh;
            o[j] = (sp - inh) * thr;
        }
        o4[base + (size_t)t * PER_B4] = make_float4(o[0], o[1], o[2], o[3]);
    }
}

// ---------------------------------------------------------------------------
extern "C" void kernel_launch(void* const* d_in, const int* in_sizes, int n_in,
                              void* d_out, int out_size)
{
    const float* x    = (const float*)d_in[0];
    const float* W    = (const float*)d_in[1];
    const float* bias = (const float*)d_in[2];
    const float* thr  = (const float*)d_in[3];
    float* out        = (float*)d_out;

    cudaFuncSetAttribute(conv_mma_kernel,
                         cudaFuncAttributeMaxDynamicSharedMemorySize, SM_TOTAL);

    pad_split_kernel<<<dim3(N_IMG, NP), 256>>>(x);
    wsplit_kernel<<<(WSTR + 255) / 256, 256>>>(W);
    conv_mma_kernel<<<dim3(N_IMG, 8), 256, SM_TOTAL>>>(bias);

    int groups = 32 * (C_IN * HH * WW) / 4;
    spike_scan_kernel<<<groups / 256, 256>>>(thr, out);
}